// round 8
// baseline (speedup 1.0000x reference)
#include <cuda_runtime.h>
#include <cuda_fp16.h>
#include <cstdint>
#include <math.h>

// LinkPredictor via mma.sync (HMMA fp16 single-pass, fp32 accum), 2 CTAs/SM.
// Round 8: fold dtype-detect into prep kernel; raise gather MLP.
// Inputs: 0:z[500000*128]f32 1:edge_index[2*E] (i32 or i64)
//         2:W1[512*128] 3:b1[128] 4:W2[128*64] 5:b2[64] 6:W3[64] 7:b3[1]
// Output: score[E] f32

#define HDIM 128
constexpr int MB      = 64;     // edges per block
constexpr int THREADS = 256;    // 8 warps

// ---- smem layout (bytes) ----
constexpr int OFF_PART = 0;         // 512 B reduction scratch
constexpr int PLANE    = 16384;     // 64 rows * 256 B
constexpr int OFF_SRC  = 512;
constexpr int OFF_DST  = OFF_SRC + PLANE;   // 16896
constexpr int OFF_A23  = OFF_DST + PLANE;   // 33280 (chunk2/3, later h1)
constexpr int OFF_W0   = OFF_A23 + PLANE;   // 49664 (32 KB buf)
constexpr int OFF_W1B  = OFF_W0 + 32768;    // 82432 (32 KB buf)
constexpr int SMEM_TOTAL = OFF_W1B + 32768; // 115200  -> 2 CTAs/SM

// preconverted, pre-swizzled weights (single fp16)
__device__ unsigned char g_W1p[4 * 32768];  // [chunk][n=128 rows][k=128 fp16]
__device__ unsigned char g_W2p[16384];      // [n=64 rows][k=128 fp16]
__device__ int g_ei_is64;

// ---- helpers ----
__device__ __forceinline__ uint32_t smem_u32(const void* p) {
    uint32_t a;
    asm("{ .reg .u64 t; cvta.to.shared.u64 t, %1; cvt.u32.u64 %0, t; }" : "=r"(a) : "l"(p));
    return a;
}
__device__ __forceinline__ void ldsm4(uint32_t& r0, uint32_t& r1, uint32_t& r2, uint32_t& r3,
                                      uint32_t addr) {
    asm volatile("ldmatrix.sync.aligned.m8n8.x4.shared.b16 {%0,%1,%2,%3}, [%4];"
        : "=r"(r0), "=r"(r1), "=r"(r2), "=r"(r3) : "r"(addr));
}
__device__ __forceinline__ void mma16816(float* c, uint32_t a0, uint32_t a1, uint32_t a2,
                                         uint32_t a3, uint32_t b0, uint32_t b1) {
    asm volatile("mma.sync.aligned.m16n8k16.row.col.f32.f16.f16.f32 "
        "{%0,%1,%2,%3}, {%4,%5,%6,%7}, {%8,%9}, {%0,%1,%2,%3};"
        : "+f"(c[0]), "+f"(c[1]), "+f"(c[2]), "+f"(c[3])
        : "r"(a0), "r"(a1), "r"(a2), "r"(a3), "r"(b0), "r"(b1));
}
__device__ __forceinline__ void cp16(uint32_t dst, const void* src) {
    asm volatile("cp.async.cg.shared.global [%0], [%1], 16;" :: "r"(dst), "l"(src));
}
#define CP_COMMIT() asm volatile("cp.async.commit_group;" ::: "memory")
template <int N> __device__ __forceinline__ void cp_wait() {
    asm volatile("cp.async.wait_group %0;" :: "n"(N) : "memory");
}

// swizzled offset within a plane: row stride 256B, 16B units XORed by row&7
__device__ __host__ __forceinline__ uint32_t aoff(int row, int k) {
    return (uint32_t)(row * 256 + (((k >> 3) ^ (row & 7)) << 4) + (k & 7) * 2);
}
__device__ __forceinline__ uint2 pack4h(float4 v) {
    uint2 r;
    __half2 p0 = __floats2half2_rn(v.x, v.y);
    __half2 p1 = __floats2half2_rn(v.z, v.w);
    r.x = *(uint32_t*)&p0;
    r.y = *(uint32_t*)&p1;
    return r;
}
__device__ __forceinline__ float hfr(uint32_t w, int hi16) {
    return __half2float(__ushort_as_half((uint16_t)(hi16 ? (w >> 16) : (w & 0xffff))));
}

// ---- setup kernel (weights + dtype detect fused) ----
__global__ void prep_weights(const float* __restrict__ W1, const float* __restrict__ W2,
                             const void* ei, int E, int n_nodes) {
    if (blockIdx.x == 0 && threadIdx.x == 0) {
        const long long* e64 = (const long long*)ei;
        int n = (E < 64) ? E : 64;
        int is64 = 1;
        for (int i = 0; i < n; i++) {
            long long v = e64[i];
            if (v < 0 || v >= (long long)n_nodes) { is64 = 0; break; }
        }
        g_ei_is64 = is64;
    }
    int idx = blockIdx.x * 256 + threadIdx.x;
    if (idx < 65536) {                       // W1[512][128]: B[n][k] = W1[c*128+k][n]
        int c = idx >> 14, e = idx & 16383;
        int n = e >> 7, k = e & 127;
        float f = W1[(c * 128 + k) * 128 + n];
        *(uint16_t*)(g_W1p + (size_t)c * 32768 + aoff(n, k)) =
            __half_as_ushort(__float2half_rn(f));
    } else if (idx < 65536 + 8192) {         // W2[128][64]: B[n][k] = W2[k][n]
        int e = idx - 65536;
        int n = e >> 7, k = e & 127;
        *(uint16_t*)(g_W2p + aoff(n, k)) =
            __half_as_ushort(__float2half_rn(W2[k * 64 + n]));
    }
}

// ---- main kernel ----
__global__ __launch_bounds__(THREADS, 2)
void lp_main(const float* __restrict__ z,
             const void* __restrict__ ei_raw,
             const float* __restrict__ b1,
             const float* __restrict__ b2,
             const float* __restrict__ W3,
             const float* __restrict__ b3,
             float* __restrict__ out,
             int E)
{
    extern __shared__ unsigned char sm[];
    const uint32_t smb = smem_u32(sm);
    const int tid  = threadIdx.x;
    const int warp = tid >> 5;
    const int lane = tid & 31;
    const int wm = warp >> 1, wn = warp & 1;
    const int m0 = wm * 16;
    const int eb = blockIdx.x * MB;

    // prefetch W1 chunk 0 -> wbuf0 (32 KB)
    {
        #pragma unroll
        for (int t = 0; t < 8; t++) {
            uint32_t o = (uint32_t)(tid + t * 256) * 16;
            cp16(smb + OFF_W0 + o, g_W1p + o);
        }
        CP_COMMIT();
    }

    // ---- gather: high-MLP index + z loads, build src/dst/prod fp16 planes ----
    {
        const int is64 = g_ei_is64;
        const long long* e64 = (const long long*)ei_raw;
        const int*       e32 = (const int*)ei_raw;

        int si[8], di[8];
        #pragma unroll
        for (int i = 0; i < 8; i++) {
            const int e = eb + warp * 8 + i;
            const int ec = (e < E) ? e : (E - 1);
            if (is64) { si[i] = (int)e64[ec]; di[i] = (int)e64[(size_t)E + ec]; }
            else      { si[i] = e32[ec];      di[i] = e32[(size_t)E + ec]; }
        }

        #pragma unroll
        for (int ib = 0; ib < 2; ib++) {
            float4 sv[4], dv[4];
            #pragma unroll
            for (int j = 0; j < 4; j++) {
                sv[j] = *(const float4*)(z + (size_t)si[ib * 4 + j] * HDIM + lane * 4);
                dv[j] = *(const float4*)(z + (size_t)di[ib * 4 + j] * HDIM + lane * 4);
            }
            #pragma unroll
            for (int j = 0; j < 4; j++) {
                const int r = warp * 8 + ib * 4 + j;
                float4 iv;
                iv.x = sv[j].x * dv[j].x; iv.y = sv[j].y * dv[j].y;
                iv.z = sv[j].z * dv[j].z; iv.w = sv[j].w * dv[j].w;
                const uint32_t o = aoff(r, lane * 4);
                *(uint2*)(sm + OFF_SRC + o) = pack4h(sv[j]);
                *(uint2*)(sm + OFF_DST + o) = pack4h(dv[j]);
                *(uint2*)(sm + OFF_A23 + o) = pack4h(iv);
            }
        }
    }

    // ---- per-thread ldmatrix geometry ----
    const int tileA = lane >> 3;
    const int rowA  = m0 + ((tileA & 1) << 3) + (lane & 7);
    const int rxA   = rowA & 7;
    const int kuA   = tileA >> 1;            // 0 or 1 (k unit offset)
    const int kuB   = (lane >> 3) & 1;
    int rowB[4], rxB[4];
    {
        const int nb = wn * 64;
        #pragma unroll
        for (int jp = 0; jp < 4; jp++) {
            rowB[jp] = nb + jp * 16 + ((lane >> 4) << 3) + (lane & 7);
            rxB[jp]  = rowB[jp] & 7;
        }
    }

    float acc[32];
    #pragma unroll
    for (int i = 0; i < 32; i++) acc[i] = 0.0f;

    static const int AOFS[4] = {OFF_SRC, OFF_DST, OFF_A23, OFF_A23};

    // ---- GEMM1: 4 K-chunks of 128 ----
    #pragma unroll 1
    for (int c = 0; c < 4; c++) {
        __syncthreads();     // prev chunk's smem reads complete

        if (c == 3) {        // rebuild A23 = |src-dst| from fp16 planes
            #pragma unroll
            for (int t = 0; t < 4; t++) {
                const int idx = tid + t * 256;      // 1024 items of 8 cols
                const int r = idx >> 4, kg = (idx & 15) * 8;
                const uint32_t o = aoff(r, kg);
                const uint4 shv = *(const uint4*)(sm + OFF_SRC + o);
                const uint4 dhv = *(const uint4*)(sm + OFF_DST + o);
                uint4 rv;
                const uint32_t* sp = &shv.x;
                const uint32_t* dp = &dhv.x;
                uint32_t* rp = &rv.x;
                #pragma unroll
                for (int q = 0; q < 4; q++) {
                    float a0 = fabsf(hfr(sp[q],0) - hfr(dp[q],0));
                    float a1 = fabsf(hfr(sp[q],1) - hfr(dp[q],1));
                    __half2 p = __floats2half2_rn(a0, a1);
                    rp[q] = *(uint32_t*)&p;
                }
                *(uint4*)(sm + OFF_A23 + o) = rv;
            }
        }

        // prefetch next W block into the other buffer
        if (c < 3) {
            const unsigned char* src = g_W1p + (size_t)(c + 1) * 32768;
            const uint32_t dst = smb + (((c + 1) & 1) ? OFF_W1B : OFF_W0);
            #pragma unroll
            for (int t = 0; t < 8; t++) {
                uint32_t o = (uint32_t)(tid + t * 256) * 16;
                cp16(dst + o, src + o);
            }
        } else {
            #pragma unroll
            for (int t = 0; t < 4; t++) {
                uint32_t o = (uint32_t)(tid + t * 256) * 16;
                cp16(smb + OFF_W0 + o, g_W2p + o);
            }
        }
        CP_COMMIT();
        cp_wait<1>();        // current chunk's W resident
        __syncthreads();

        const uint32_t ab = smb + AOFS[c] + rowA * 256;
        const uint32_t wb = smb + ((c & 1) ? OFF_W1B : OFF_W0);
        uint32_t whb[4];
        #pragma unroll
        for (int jp = 0; jp < 4; jp++) whb[jp] = wb + rowB[jp] * 256;

        #pragma unroll
        for (int ks = 0; ks < 8; ks++) {
            const int kq = ks * 2;
            uint32_t a0, a1, a2, a3;
            const uint32_t ao = (uint32_t)((kq + kuA) ^ rxA) << 4;
            ldsm4(a0, a1, a2, a3, ab + ao);
            uint32_t bh[16];
            #pragma unroll
            for (int jp = 0; jp < 4; jp++) {
                const uint32_t bo = (uint32_t)((kq + kuB) ^ rxB[jp]) << 4;
                ldsm4(bh[4*jp], bh[4*jp+1], bh[4*jp+2], bh[4*jp+3], whb[jp] + bo);
            }
            #pragma unroll
            for (int j = 0; j < 8; j++)
                mma16816(&acc[4*j], a0, a1, a2, a3, bh[2*j], bh[2*j+1]);
        }
    }

    // ---- epilogue1: h1 = relu(C1 + b1) -> fp16 into A23 plane ----
    __syncthreads();   // GEMM1 reads of A23 complete
    {
        const int r1 = m0 + (lane >> 2);
        #pragma unroll
        for (int j = 0; j < 8; j++) {
            const int col = wn * 64 + j * 8 + (lane & 3) * 2;
            const float ba = __ldg(b1 + col), bb = __ldg(b1 + col + 1);
            __half2 p0 = __floats2half2_rn(fmaxf(acc[4*j]   + ba, 0.0f),
                                           fmaxf(acc[4*j+1] + bb, 0.0f));
            __half2 p1 = __floats2half2_rn(fmaxf(acc[4*j+2] + ba, 0.0f),
                                           fmaxf(acc[4*j+3] + bb, 0.0f));
            *(uint32_t*)(sm + OFF_A23 + aoff(r1, col))     = *(uint32_t*)&p0;
            *(uint32_t*)(sm + OFF_A23 + aoff(r1 + 8, col)) = *(uint32_t*)&p1;
        }
    }
    cp_wait<0>();       // W2 resident
    __syncthreads();

    // ---- GEMM2: C2[64][64] = h1 @ W2 ----
    float acc2[16];
    #pragma unroll
    for (int i = 0; i < 16; i++) acc2[i] = 0.0f;
    {
        const uint32_t ab = smb + OFF_A23 + rowA * 256;
        int rowB2[2], rxB2[2];
        #pragma unroll
        for (int jp = 0; jp < 2; jp++) {
            rowB2[jp] = wn * 32 + jp * 16 + ((lane >> 4) << 3) + (lane & 7);
            rxB2[jp]  = rowB2[jp] & 7;
        }
        #pragma unroll
        for (int ks = 0; ks < 8; ks++) {
            const int kq = ks * 2;
            uint32_t a0, a1, a2, a3;
            const uint32_t ao = (uint32_t)((kq + kuA) ^ rxA) << 4;
            ldsm4(a0, a1, a2, a3, ab + ao);
            uint32_t bh[8];
            #pragma unroll
            for (int jp = 0; jp < 2; jp++) {
                const uint32_t wbase = smb + OFF_W0 + rowB2[jp] * 256;
                const uint32_t bo = (uint32_t)((kq + kuB) ^ rxB2[jp]) << 4;
                ldsm4(bh[4*jp], bh[4*jp+1], bh[4*jp+2], bh[4*jp+3], wbase + bo);
            }
            #pragma unroll
            for (int j = 0; j < 4; j++)
                mma16816(&acc2[4*j], a0, a1, a2, a3, bh[2*j], bh[2*j+1]);
        }
    }

    // ---- epilogue2: score = relu(C2 + b2) . W3 (+b3) ----
    {
        float p1 = 0.0f, p2 = 0.0f;
        #pragma unroll
        for (int j = 0; j < 4; j++) {
            const int col = wn * 32 + j * 8 + (lane & 3) * 2;
            const float ba = __ldg(b2 + col), bb = __ldg(b2 + col + 1);
            const float wa = __ldg(W3 + col), wwb = __ldg(W3 + col + 1);
            p1 += fmaxf(acc2[4*j]   + ba, 0.0f) * wa;
            p1 += fmaxf(acc2[4*j+1] + bb, 0.0f) * wwb;
            p2 += fmaxf(acc2[4*j+2] + ba, 0.0f) * wa;
            p2 += fmaxf(acc2[4*j+3] + bb, 0.0f) * wwb;
        }
        p1 += __shfl_xor_sync(0xffffffff, p1, 1);
        p1 += __shfl_xor_sync(0xffffffff, p1, 2);
        p2 += __shfl_xor_sync(0xffffffff, p2, 1);
        p2 += __shfl_xor_sync(0xffffffff, p2, 2);
        float* part = (float*)(sm + OFF_PART);
        if ((lane & 3) == 0) {
            const int r1 = m0 + (lane >> 2);
            part[wn * 64 + r1]     = p1;
            part[wn * 64 + r1 + 8] = p2;
        }
    }
    __syncthreads();
    if (tid < MB) {
        const float* part = (const float*)(sm + OFF_PART);
        const int e = eb + tid;
        if (e < E) out[e] = part[tid] + part[64 + tid] + __ldg(b3);
    }
}

// ---- launcher ----
extern "C" void kernel_launch(void* const* d_in, const int* in_sizes, int n_in,
                              void* d_out, int out_size)
{
    const float* z  = (const float*)d_in[0];
    const void*  ei = d_in[1];
    const float* W1 = (const float*)d_in[2];
    const float* b1 = (const float*)d_in[3];
    const float* W2 = (const float*)d_in[4];
    const float* b2 = (const float*)d_in[5];
    const float* W3 = (const float*)d_in[6];
    const float* b3 = (const float*)d_in[7];
    float* out = (float*)d_out;

    const int E = out_size;
    const int n_nodes = in_sizes[0] / HDIM;

    static bool attr_set = false;
    if (!attr_set) {
        cudaFuncSetAttribute(lp_main, cudaFuncAttributeMaxDynamicSharedMemorySize, SMEM_TOTAL);
        attr_set = true;
    }

    prep_weights<<<288, 256>>>(W1, W2, ei, E, n_nodes);

    const int grid = (E + MB - 1) / MB;
    lp_main<<<grid, THREADS, SMEM_TOTAL>>>(z, ei, b1, b2, W3, b3, out, E);
}

// round 9
// speedup vs baseline: 1.0924x; 1.0924x over previous
#include <cuda_runtime.h>
#include <cuda_fp16.h>
#include <cstdint>
#include <math.h>

// LinkPredictor via mma.sync (HMMA fp16 single-pass, fp32 accum).
// Round 9: MB=128, warp tile m32xn64 -> LDSM/MMA 0.625->0.375 (smem-BW bound fix).
// Inputs: 0:z[500000*128]f32 1:edge_index[2*E] (i32 or i64)
//         2:W1[512*128] 3:b1[128] 4:W2[128*64] 5:b2[64] 6:W3[64] 7:b3[1]
// Output: score[E] f32

#define HDIM 128
constexpr int MB      = 128;    // edges per block
constexpr int THREADS = 256;    // 8 warps: 4m x 2n, warp tile m32 x n64

// ---- smem layout (bytes) ----
constexpr int OFF_PART = 0;         // 1024 B reduction scratch (2x128 floats)
constexpr int PLANE    = 32768;     // 128 rows * 256 B
constexpr int OFF_SRC  = 1024;
constexpr int OFF_DST  = OFF_SRC + PLANE;   // 33792
constexpr int OFF_A23  = OFF_DST + PLANE;   // 66560 (chunk2/3, later h1)
constexpr int OFF_W0   = OFF_A23 + PLANE;   // 99328  (32 KB buf)
constexpr int OFF_W1B  = OFF_W0 + 32768;    // 132096 (32 KB buf)
constexpr int SMEM_TOTAL = OFF_W1B + 32768; // 164864 -> 1 CTA/SM

// preconverted, pre-swizzled weights (single fp16)
__device__ unsigned char g_W1p[4 * 32768];  // [chunk][n=128 rows][k=128 fp16]
__device__ unsigned char g_W2p[16384];      // [n=64 rows][k=128 fp16]
__device__ int g_ei_is64;

// ---- helpers ----
__device__ __forceinline__ uint32_t smem_u32(const void* p) {
    uint32_t a;
    asm("{ .reg .u64 t; cvta.to.shared.u64 t, %1; cvt.u32.u64 %0, t; }" : "=r"(a) : "l"(p));
    return a;
}
__device__ __forceinline__ void ldsm4(uint32_t& r0, uint32_t& r1, uint32_t& r2, uint32_t& r3,
                                      uint32_t addr) {
    asm volatile("ldmatrix.sync.aligned.m8n8.x4.shared.b16 {%0,%1,%2,%3}, [%4];"
        : "=r"(r0), "=r"(r1), "=r"(r2), "=r"(r3) : "r"(addr));
}
__device__ __forceinline__ void mma16816(float* c, uint32_t a0, uint32_t a1, uint32_t a2,
                                         uint32_t a3, uint32_t b0, uint32_t b1) {
    asm volatile("mma.sync.aligned.m16n8k16.row.col.f32.f16.f16.f32 "
        "{%0,%1,%2,%3}, {%4,%5,%6,%7}, {%8,%9}, {%0,%1,%2,%3};"
        : "+f"(c[0]), "+f"(c[1]), "+f"(c[2]), "+f"(c[3])
        : "r"(a0), "r"(a1), "r"(a2), "r"(a3), "r"(b0), "r"(b1));
}
__device__ __forceinline__ void cp16(uint32_t dst, const void* src) {
    asm volatile("cp.async.cg.shared.global [%0], [%1], 16;" :: "r"(dst), "l"(src));
}
#define CP_COMMIT() asm volatile("cp.async.commit_group;" ::: "memory")
template <int N> __device__ __forceinline__ void cp_wait() {
    asm volatile("cp.async.wait_group %0;" :: "n"(N) : "memory");
}

// swizzled offset within a plane: row stride 256B, 16B units XORed by row&7
__device__ __host__ __forceinline__ uint32_t aoff(int row, int k) {
    return (uint32_t)(row * 256 + (((k >> 3) ^ (row & 7)) << 4) + (k & 7) * 2);
}
__device__ __forceinline__ uint2 pack4h(float4 v) {
    uint2 r;
    __half2 p0 = __floats2half2_rn(v.x, v.y);
    __half2 p1 = __floats2half2_rn(v.z, v.w);
    r.x = *(uint32_t*)&p0;
    r.y = *(uint32_t*)&p1;
    return r;
}
__device__ __forceinline__ float hfr(uint32_t w, int hi16) {
    return __half2float(__ushort_as_half((uint16_t)(hi16 ? (w >> 16) : (w & 0xffff))));
}

// ---- setup kernel (weights + dtype detect fused) ----
__global__ void prep_weights(const float* __restrict__ W1, const float* __restrict__ W2,
                             const void* ei, int E, int n_nodes) {
    if (blockIdx.x == 0 && threadIdx.x == 0) {
        const long long* e64 = (const long long*)ei;
        int n = (E < 64) ? E : 64;
        int is64 = 1;
        for (int i = 0; i < n; i++) {
            long long v = e64[i];
            if (v < 0 || v >= (long long)n_nodes) { is64 = 0; break; }
        }
        g_ei_is64 = is64;
    }
    int idx = blockIdx.x * 256 + threadIdx.x;
    if (idx < 65536) {                       // W1[512][128]: B[n][k] = W1[c*128+k][n]
        int c = idx >> 14, e = idx & 16383;
        int n = e >> 7, k = e & 127;
        float f = W1[(c * 128 + k) * 128 + n];
        *(uint16_t*)(g_W1p + (size_t)c * 32768 + aoff(n, k)) =
            __half_as_ushort(__float2half_rn(f));
    } else if (idx < 65536 + 8192) {         // W2[128][64]: B[n][k] = W2[k][n]
        int e = idx - 65536;
        int n = e >> 7, k = e & 127;
        *(uint16_t*)(g_W2p + aoff(n, k)) =
            __half_as_ushort(__float2half_rn(W2[k * 64 + n]));
    }
}

// ---- main kernel ----
__global__ __launch_bounds__(THREADS, 1)
void lp_main(const float* __restrict__ z,
             const void* __restrict__ ei_raw,
             const float* __restrict__ b1,
             const float* __restrict__ b2,
             const float* __restrict__ W3,
             const float* __restrict__ b3,
             float* __restrict__ out,
             int E)
{
    extern __shared__ unsigned char sm[];
    const uint32_t smb = smem_u32(sm);
    const int tid  = threadIdx.x;
    const int warp = tid >> 5;
    const int lane = tid & 31;
    const int wm = warp >> 1, wn = warp & 1;
    const int m0 = wm * 32;                  // warp owns rows m0..m0+31
    const int eb = blockIdx.x * MB;

    // prefetch W1 chunk 0 -> wbuf0 (32 KB)
    {
        #pragma unroll
        for (int t = 0; t < 8; t++) {
            uint32_t o = (uint32_t)(tid + t * 256) * 16;
            cp16(smb + OFF_W0 + o, g_W1p + o);
        }
        CP_COMMIT();
    }

    // ---- gather: 16 edges per warp, high-MLP ----
    {
        const int is64 = g_ei_is64;
        const long long* e64 = (const long long*)ei_raw;
        const int*       e32 = (const int*)ei_raw;

        int si[16], di[16];
        #pragma unroll
        for (int i = 0; i < 16; i++) {
            const int e = eb + warp * 16 + i;
            const int ec = (e < E) ? e : (E - 1);
            if (is64) { si[i] = (int)e64[ec]; di[i] = (int)e64[(size_t)E + ec]; }
            else      { si[i] = e32[ec];      di[i] = e32[(size_t)E + ec]; }
        }

        #pragma unroll
        for (int ib = 0; ib < 4; ib++) {
            float4 sv[4], dv[4];
            #pragma unroll
            for (int j = 0; j < 4; j++) {
                sv[j] = *(const float4*)(z + (size_t)si[ib * 4 + j] * HDIM + lane * 4);
                dv[j] = *(const float4*)(z + (size_t)di[ib * 4 + j] * HDIM + lane * 4);
            }
            #pragma unroll
            for (int j = 0; j < 4; j++) {
                const int r = warp * 16 + ib * 4 + j;
                float4 iv;
                iv.x = sv[j].x * dv[j].x; iv.y = sv[j].y * dv[j].y;
                iv.z = sv[j].z * dv[j].z; iv.w = sv[j].w * dv[j].w;
                const uint32_t o = aoff(r, lane * 4);
                *(uint2*)(sm + OFF_SRC + o) = pack4h(sv[j]);
                *(uint2*)(sm + OFF_DST + o) = pack4h(dv[j]);
                *(uint2*)(sm + OFF_A23 + o) = pack4h(iv);
            }
        }
    }

    // ---- per-thread ldmatrix geometry ----
    const int tileA = lane >> 3;
    const int rowA0 = m0 + ((tileA & 1) << 3) + (lane & 7);   // frag 0 (rows m0..m0+15)
    const int rxA   = rowA0 & 7;                              // same parity for frag1 (+16)
    const int kuA   = tileA >> 1;
    const int kuB   = (lane >> 3) & 1;
    int rowB[4], rxB[4];
    {
        const int nb = wn * 64;
        #pragma unroll
        for (int jp = 0; jp < 4; jp++) {
            rowB[jp] = nb + jp * 16 + ((lane >> 4) << 3) + (lane & 7);
            rxB[jp]  = rowB[jp] & 7;
        }
    }

    float acc[2][32];
    #pragma unroll
    for (int f = 0; f < 2; f++)
        #pragma unroll
        for (int i = 0; i < 32; i++) acc[f][i] = 0.0f;

    static const int AOFS[4] = {OFF_SRC, OFF_DST, OFF_A23, OFF_A23};

    // ---- GEMM1: 4 K-chunks of 128 ----
    #pragma unroll 1
    for (int c = 0; c < 4; c++) {
        __syncthreads();     // prev chunk's smem reads complete

        if (c == 3) {        // rebuild A23 = |src-dst| from fp16 planes
            #pragma unroll
            for (int t = 0; t < 8; t++) {
                const int idx = tid + t * 256;      // 2048 items of 8 cols
                const int r = idx >> 4, kg = (idx & 15) * 8;
                const uint32_t o = aoff(r, kg);
                const uint4 shv = *(const uint4*)(sm + OFF_SRC + o);
                const uint4 dhv = *(const uint4*)(sm + OFF_DST + o);
                uint4 rv;
                const uint32_t* sp = &shv.x;
                const uint32_t* dp = &dhv.x;
                uint32_t* rp = &rv.x;
                #pragma unroll
                for (int q = 0; q < 4; q++) {
                    float a0 = fabsf(hfr(sp[q],0) - hfr(dp[q],0));
                    float a1 = fabsf(hfr(sp[q],1) - hfr(dp[q],1));
                    __half2 p = __floats2half2_rn(a0, a1);
                    rp[q] = *(uint32_t*)&p;
                }
                *(uint4*)(sm + OFF_A23 + o) = rv;
            }
        }

        // prefetch next W block into the other buffer
        if (c < 3) {
            const unsigned char* src = g_W1p + (size_t)(c + 1) * 32768;
            const uint32_t dst = smb + (((c + 1) & 1) ? OFF_W1B : OFF_W0);
            #pragma unroll
            for (int t = 0; t < 8; t++) {
                uint32_t o = (uint32_t)(tid + t * 256) * 16;
                cp16(dst + o, src + o);
            }
        } else {
            #pragma unroll
            for (int t = 0; t < 4; t++) {
                uint32_t o = (uint32_t)(tid + t * 256) * 16;
                cp16(smb + OFF_W0 + o, g_W2p + o);
            }
        }
        CP_COMMIT();
        cp_wait<1>();        // current chunk's W resident
        __syncthreads();

        const uint32_t ab0 = smb + AOFS[c] + rowA0 * 256;
        const uint32_t ab1 = ab0 + 16 * 256;
        const uint32_t wb  = smb + ((c & 1) ? OFF_W1B : OFF_W0);
        uint32_t whb[4];
        #pragma unroll
        for (int jp = 0; jp < 4; jp++) whb[jp] = wb + rowB[jp] * 256;

        #pragma unroll
        for (int ks = 0; ks < 8; ks++) {
            const int kq = ks * 2;
            const uint32_t ao = (uint32_t)((kq + kuA) ^ rxA) << 4;
            uint32_t a0, a1, a2, a3, a4, a5, a6, a7;
            ldsm4(a0, a1, a2, a3, ab0 + ao);
            ldsm4(a4, a5, a6, a7, ab1 + ao);
            uint32_t bh[16];
            #pragma unroll
            for (int jp = 0; jp < 4; jp++) {
                const uint32_t bo = (uint32_t)((kq + kuB) ^ rxB[jp]) << 4;
                ldsm4(bh[4*jp], bh[4*jp+1], bh[4*jp+2], bh[4*jp+3], whb[jp] + bo);
            }
            #pragma unroll
            for (int j = 0; j < 8; j++)
                mma16816(&acc[0][4*j], a0, a1, a2, a3, bh[2*j], bh[2*j+1]);
            #pragma unroll
            for (int j = 0; j < 8; j++)
                mma16816(&acc[1][4*j], a4, a5, a6, a7, bh[2*j], bh[2*j+1]);
        }
    }

    // ---- epilogue1: h1 = relu(C1 + b1) -> fp16 into A23 plane ----
    __syncthreads();   // GEMM1 reads of A23 complete
    {
        #pragma unroll
        for (int f = 0; f < 2; f++) {
            const int r1 = m0 + f * 16 + (lane >> 2);
            #pragma unroll
            for (int j = 0; j < 8; j++) {
                const int col = wn * 64 + j * 8 + (lane & 3) * 2;
                const float ba = __ldg(b1 + col), bb = __ldg(b1 + col + 1);
                __half2 p0 = __floats2half2_rn(fmaxf(acc[f][4*j]   + ba, 0.0f),
                                               fmaxf(acc[f][4*j+1] + bb, 0.0f));
                __half2 p1 = __floats2half2_rn(fmaxf(acc[f][4*j+2] + ba, 0.0f),
                                               fmaxf(acc[f][4*j+3] + bb, 0.0f));
                *(uint32_t*)(sm + OFF_A23 + aoff(r1, col))     = *(uint32_t*)&p0;
                *(uint32_t*)(sm + OFF_A23 + aoff(r1 + 8, col)) = *(uint32_t*)&p1;
            }
        }
    }
    cp_wait<0>();       // W2 resident
    __syncthreads();

    // ---- GEMM2: C2[128][64] = h1 @ W2, warp tile m32 x n32 ----
    float acc2[2][16];
    #pragma unroll
    for (int f = 0; f < 2; f++)
        #pragma unroll
        for (int i = 0; i < 16; i++) acc2[f][i] = 0.0f;
    {
        const uint32_t ab0 = smb + OFF_A23 + rowA0 * 256;
        const uint32_t ab1 = ab0 + 16 * 256;
        int rowB2[2], rxB2[2];
        #pragma unroll
        for (int jp = 0; jp < 2; jp++) {
            rowB2[jp] = wn * 32 + jp * 16 + ((lane >> 4) << 3) + (lane & 7);
            rxB2[jp]  = rowB2[jp] & 7;
        }
        #pragma unroll
        for (int ks = 0; ks < 8; ks++) {
            const int kq = ks * 2;
            const uint32_t ao = (uint32_t)((kq + kuA) ^ rxA) << 4;
            uint32_t a0, a1, a2, a3, a4, a5, a6, a7;
            ldsm4(a0, a1, a2, a3, ab0 + ao);
            ldsm4(a4, a5, a6, a7, ab1 + ao);
            uint32_t bh[8];
            #pragma unroll
            for (int jp = 0; jp < 2; jp++) {
                const uint32_t wbase = smb + OFF_W0 + rowB2[jp] * 256;
                const uint32_t bo = (uint32_t)((kq + kuB) ^ rxB2[jp]) << 4;
                ldsm4(bh[4*jp], bh[4*jp+1], bh[4*jp+2], bh[4*jp+3], wbase + bo);
            }
            #pragma unroll
            for (int j = 0; j < 4; j++)
                mma16816(&acc2[0][4*j], a0, a1, a2, a3, bh[2*j], bh[2*j+1]);
            #pragma unroll
            for (int j = 0; j < 4; j++)
                mma16816(&acc2[1][4*j], a4, a5, a6, a7, bh[2*j], bh[2*j+1]);
        }
    }

    // ---- epilogue2: score = relu(C2 + b2) . W3 (+b3) ----
    {
        float* part = (float*)(sm + OFF_PART);
        #pragma unroll
        for (int f = 0; f < 2; f++) {
            float p1 = 0.0f, p2 = 0.0f;
            #pragma unroll
            for (int j = 0; j < 4; j++) {
                const int col = wn * 32 + j * 8 + (lane & 3) * 2;
                const float ba = __ldg(b2 + col), bb = __ldg(b2 + col + 1);
                const float wa = __ldg(W3 + col), wwb = __ldg(W3 + col + 1);
                p1 += fmaxf(acc2[f][4*j]   + ba, 0.0f) * wa;
                p1 += fmaxf(acc2[f][4*j+1] + bb, 0.0f) * wwb;
                p2 += fmaxf(acc2[f][4*j+2] + ba, 0.0f) * wa;
                p2 += fmaxf(acc2[f][4*j+3] + bb, 0.0f) * wwb;
            }
            p1 += __shfl_xor_sync(0xffffffff, p1, 1);
            p1 += __shfl_xor_sync(0xffffffff, p1, 2);
            p2 += __shfl_xor_sync(0xffffffff, p2, 1);
            p2 += __shfl_xor_sync(0xffffffff, p2, 2);
            if ((lane & 3) == 0) {
                const int r1 = m0 + f * 16 + (lane >> 2);
                part[wn * 128 + r1]     = p1;
                part[wn * 128 + r1 + 8] = p2;
            }
        }
    }
    __syncthreads();
    if (tid < MB) {
        const float* part = (const float*)(sm + OFF_PART);
        const int e = eb + tid;
        if (e < E) out[e] = part[tid] + part[128 + tid] + __ldg(b3);
    }
}

// ---- launcher ----
extern "C" void kernel_launch(void* const* d_in, const int* in_sizes, int n_in,
                              void* d_out, int out_size)
{
    const float* z  = (const float*)d_in[0];
    const void*  ei = d_in[1];
    const float* W1 = (const float*)d_in[2];
    const float* b1 = (const float*)d_in[3];
    const float* W2 = (const float*)d_in[4];
    const float* b2 = (const float*)d_in[5];
    const float* W3 = (const float*)d_in[6];
    const float* b3 = (const float*)d_in[7];
    float* out = (float*)d_out;

    const int E = out_size;
    const int n_nodes = in_sizes[0] / HDIM;

    static bool attr_set = false;
    if (!attr_set) {
        cudaFuncSetAttribute(lp_main, cudaFuncAttributeMaxDynamicSharedMemorySize, SMEM_TOTAL);
        attr_set = true;
    }

    prep_weights<<<288, 256>>>(W1, W2, ei, E, n_nodes);

    const int grid = (E + MB - 1) / MB;
    lp_main<<<grid, THREADS, SMEM_TOTAL>>>(z, ei, b1, b2, W3, b3, out, E);
}